// round 16
// baseline (speedup 1.0000x reference)
#include <cuda_runtime.h>

#define NN   116
#define HID  64
#define ENCD 122

// ---- device scratch ----
__device__ float g_dv[NN];
__device__ __align__(16) float g_x1[NN * HID];
__device__ __align__(16) float g_Wc[HID * 4];    // W2 @ Wl
__device__ float g_S[NN * 5];

__device__ __forceinline__ int rowoff(int a) { return a * (231 - a) / 2; }
__device__ __forceinline__ int eix(int a, int b) { return rowoff(a) + (b - a - 1); }

// ============================================================================
// K1 (116 x 512): block per node i. Phase-0 batches all loads (float2/float4);
// GEMV stages use warp-owned m-quads + shuffle reductions (5 barriers total).
// No gE writes (k2/k3 recompute from ea in their PDL preamble).
// ============================================================================
__global__ void __launch_bounds__(512, 1) k1(
    const float* __restrict__ enc, const float* __restrict__ ea,
    const float* __restrict__ W_enc, const float* __restrict__ b_enc,
    const float* __restrict__ W1, const float* __restrict__ b1,
    const float* __restrict__ p1, const float* __restrict__ pe)
{
    __shared__ float sd1[120];            // [115..119] = 0
    __shared__ float sMp[8 * 123];
    __shared__ float sM[128];             // [122]=bias lane, [123..127]=0
    __shared__ float sy[64];
    __shared__ float sx1[64];

    const int i = blockIdx.x, t = threadIdx.x;
    const int g8 = t >> 6, c2 = t & 63;   // M stage ids
    const int w = t >> 5, lane = t & 31;  // GEMV stage: warp w owns m-quad 4w

    // ---------- Phase 0: batch-issue ALL global loads ----------
    float a5[5];
    const bool eact = t < 115;
    if (eact) {
        int k = t + (t >= i);
        int a = min(i, k), b = max(i, k);
        const float* A = ea + eix(a, b) * 5;
        #pragma unroll
        for (int c = 0; c < 5; c++) a5[c] = A[c];
    }
    // enc: col pair (2c2, 2c2+1), 15-row slice g8 — warp-contiguous float2
    float2 rE2[15];
    #pragma unroll
    for (int j = 0; j < 15; ++j) {
        int u = g8 * 15 + j;
        float2 v = make_float2(0.f, 0.f);
        if (c2 < 61 && u < 115) {
            int k = u + (u >= i);
            v = *reinterpret_cast<const float2*>(enc + k * ENCD + 2 * c2);
        }
        rE2[j] = v;
    }
    // y-stage weights: rows c = lane + 32j of [W_enc; b_enc; 0], m-quad 4w (float4)
    float4 rWz4[4];
    #pragma unroll
    for (int j = 0; j < 4; ++j) {
        int c = lane + 32 * j;
        float4 v = make_float4(0.f, 0.f, 0.f, 0.f);
        if (c < 122)       v = *reinterpret_cast<const float4*>(W_enc + c * HID + 4 * w);
        else if (c == 122) v = *reinterpret_cast<const float4*>(b_enc + 4 * w);
        rWz4[j] = v;
    }
    // x1-stage weights: rows c = lane, lane+32 of W1, m-quad 4w (float4)
    float4 rW14[2];
    #pragma unroll
    for (int j = 0; j < 2; ++j) {
        int c = lane + 32 * j;
        rW14[j] = *reinterpret_cast<const float4*>(W1 + c * HID + 4 * w);
    }
    float4 rb1q = *reinterpret_cast<const float4*>(b1 + 4 * w);
    float rpe0 = 0.f, rpe1 = 0.f;
    if (t < 32) { rpe0 = pe[t]; rpe1 = pe[t + 32]; }

    // ---------- d1 ----------
    if (eact) {
        sd1[t] = a5[0] * __ldg(&p1[0]) + a5[1] * __ldg(&p1[1]) + a5[2] * __ldg(&p1[2])
               + a5[3] * __ldg(&p1[3]) + a5[4] * __ldg(&p1[4]);
    }
    if (t >= 115 && t < 120) sd1[t] = 0.f;
    __syncthreads();                                           // BAR 1

    // ---------- M stage ----------
    if (c2 < 61) {
        float s0 = 0.f, s1 = 0.f;
        #pragma unroll
        for (int j = 0; j < 15; ++j) {
            float d = sd1[g8 * 15 + j];
            s0 += rE2[j].x * d;
            s1 += rE2[j].y * d;
        }
        sMp[g8 * 123 + 2 * c2]     = s0;
        sMp[g8 * 123 + 2 * c2 + 1] = s1;
    } else if (c2 == 61) {                // bias lane: plain sum of d1
        float s = 0.f;
        #pragma unroll
        for (int j = 0; j < 15; ++j) {
            int u = g8 * 15 + j;
            if (u < 115) s += sd1[u];
        }
        sMp[g8 * 123 + 122] = s;
    }
    __syncthreads();                                           // BAR 2
    if (t < 123) {
        float s = 0.f;
        #pragma unroll
        for (int q = 0; q < 8; ++q) s += sMp[q * 123 + t];
        sM[t] = s;
    }
    if (t >= 123 && t < 128) sM[t] = 0.f;
    __syncthreads();                                           // BAR 3

    // ---------- y[4w..4w+3] = Σ_c M[c] * Wz[c][.] (warp-local shuffle) ----------
    {
        float p0 = 0.f, p1v = 0.f, p2v = 0.f, p3 = 0.f;
        #pragma unroll
        for (int j = 0; j < 4; ++j) {
            float mv = sM[lane + 32 * j];  // c >= 124 lanes read sM pad (=0)
            p0 += mv * rWz4[j].x; p1v += mv * rWz4[j].y;
            p2v += mv * rWz4[j].z; p3 += mv * rWz4[j].w;
        }
        #pragma unroll
        for (int off = 16; off; off >>= 1) {
            p0  += __shfl_xor_sync(0xffffffffu, p0, off);
            p1v += __shfl_xor_sync(0xffffffffu, p1v, off);
            p2v += __shfl_xor_sync(0xffffffffu, p2v, off);
            p3  += __shfl_xor_sync(0xffffffffu, p3, off);
        }
        if (lane == 0) {
            sy[4 * w]     = p0;
            sy[4 * w + 1] = p1v;
            sy[4 * w + 2] = p2v;
            sy[4 * w + 3] = p3;
        }
    }
    __syncthreads();                                           // BAR 4

    // ---------- x1[4w..4w+3] = relu(b1 + Σ_c y[c] * W1[c][.]) ----------
    {
        float p0 = 0.f, p1v = 0.f, p2v = 0.f, p3 = 0.f;
        #pragma unroll
        for (int j = 0; j < 2; ++j) {
            float yv = sy[lane + 32 * j];
            p0 += yv * rW14[j].x; p1v += yv * rW14[j].y;
            p2v += yv * rW14[j].z; p3 += yv * rW14[j].w;
        }
        #pragma unroll
        for (int off = 16; off; off >>= 1) {
            p0  += __shfl_xor_sync(0xffffffffu, p0, off);
            p1v += __shfl_xor_sync(0xffffffffu, p1v, off);
            p2v += __shfl_xor_sync(0xffffffffu, p2v, off);
            p3  += __shfl_xor_sync(0xffffffffu, p3, off);
        }
        if (lane == 0) {
            float4 xq = make_float4(fmaxf(rb1q.x + p0, 0.f),  fmaxf(rb1q.y + p1v, 0.f),
                                    fmaxf(rb1q.z + p2v, 0.f), fmaxf(rb1q.w + p3, 0.f));
            sx1[4 * w]     = xq.x;
            sx1[4 * w + 1] = xq.y;
            sx1[4 * w + 2] = xq.z;
            sx1[4 * w + 3] = xq.w;
            *reinterpret_cast<float4*>(g_x1 + i * HID + 4 * w) = xq;
        }
    }
    __syncthreads();                                           // BAR 5

    // ---------- dv = x1 . pe ----------
    if (t < 32) {
        float s = sx1[t] * rpe0 + sx1[t + 32] * rpe1;
        #pragma unroll
        for (int off = 16; off; off >>= 1) s += __shfl_xor_sync(0xffffffffu, s, off);
        if (t == 0) g_dv[i] = s;
    }
}

// ============================================================================
// K2 (PDL): blocks 0..115: S[i,c] with gg recomputed from ea in PREAMBLE
// (overlaps k1). Blocks 116,117: Wc = W2@Wl + bias seed (no sync needed).
// ============================================================================
__global__ void __launch_bounds__(128, 1) k2(
    const float* __restrict__ ea, const float* __restrict__ We,
    const float* __restrict__ W2, const float* __restrict__ b2,
    const float* __restrict__ Wl, const float* __restrict__ bl,
    float* __restrict__ out)
{
    const int i = blockIdx.x, t = threadIdx.x;

    if (i >= NN) {
        int idx = (i - NN) * 128 + t;    // 0..255
        int k = idx >> 2, o = idx & 3;
        float s = 0.f;
        #pragma unroll
        for (int mm = 0; mm < HID; mm++) s += W2[k * HID + mm] * Wl[mm * 4 + o];
        g_Wc[idx] = s;
        if (i == NN && t < 4) {
            float v = bl[t];
            #pragma unroll
            for (int mm = 0; mm < HID; mm++) v += b2[mm] * Wl[mm * 4 + t];
            out[t] = v;
        }
        return;
    }

    __shared__ float sdv[NN];
    __shared__ float wsum[4 * 5];
    const int wq = t >> 5, lane = t & 31;

    // ---- PREAMBLE (overlaps k1): gg from ea + We ----
    float gg[5] = {0.f, 0.f, 0.f, 0.f, 0.f};
    int kn = 0;
    const bool eact = t < 115;
    if (eact) {
        kn = t + (t >= i);
        int a = min(i, kn), b = max(i, kn);
        const float* A = ea + eix(a, b) * 5;
        float r5[5];
        #pragma unroll
        for (int c = 0; c < 5; c++) r5[c] = fmaxf(A[c], 0.f);
        #pragma unroll
        for (int cc = 0; cc < 5; cc++) {
            gg[cc] = r5[0] * __ldg(&We[cc]) + r5[1] * __ldg(&We[5 + cc])
                   + r5[2] * __ldg(&We[10 + cc]) + r5[3] * __ldg(&We[15 + cc])
                   + r5[4] * __ldg(&We[20 + cc]);
        }
    }

    cudaGridDependencySynchronize();     // k1 done: dv valid

    if (t < NN) sdv[t] = g_dv[t];
    __syncthreads();

    float s5[5] = {0.f, 0.f, 0.f, 0.f, 0.f};
    if (eact) {
        float inv = 1.f / (fmaxf(fmaxf(sdv[i], sdv[kn]), 0.f) + 1e-10f);
        #pragma unroll
        for (int c = 0; c < 5; c++) s5[c] = gg[c] * inv;
    }
    #pragma unroll
    for (int c = 0; c < 5; c++) {
        #pragma unroll
        for (int off = 16; off; off >>= 1) s5[c] += __shfl_xor_sync(0xffffffffu, s5[c], off);
        if (lane == 0) wsum[wq * 5 + c] = s5[c];
    }
    __syncthreads();
    if (t < 5) g_S[i * 5 + t] = wsum[t] + wsum[5 + t] + wsum[10 + t] + wsum[15 + t];
}

// ============================================================================
// K3 (PDL): gg preamble (overlaps k2); post-sync: dv/S/x1/Wc batched loads,
// D[i], q = x1@Wc, atomic out.
// ============================================================================
__global__ void __launch_bounds__(128, 1) k3(
    const float* __restrict__ ea, const float* __restrict__ We,
    const float* __restrict__ be, const float* __restrict__ p2,
    float* __restrict__ out)
{
    __shared__ float sdv[NN];
    __shared__ float sS[NN * 5];
    __shared__ float sx1r[HID];
    __shared__ __align__(16) float sWc[HID * 4];
    __shared__ float wred[4];
    const int i = blockIdx.x, t = threadIdx.x;
    const int wq = t >> 5, lane = t & 31;

    // ---- PREAMBLE: gg from ea + We, constants ----
    float gg[5] = {0.f, 0.f, 0.f, 0.f, 0.f};
    int kn = 0;
    const bool eact = t < 115;
    if (eact) {
        kn = t + (t >= i);
        int a = min(i, kn), b = max(i, kn);
        const float* A = ea + eix(a, b) * 5;
        float r5[5];
        #pragma unroll
        for (int c = 0; c < 5; c++) r5[c] = fmaxf(A[c], 0.f);
        #pragma unroll
        for (int cc = 0; cc < 5; cc++) {
            gg[cc] = r5[0] * __ldg(&We[cc]) + r5[1] * __ldg(&We[5 + cc])
                   + r5[2] * __ldg(&We[10 + cc]) + r5[3] * __ldg(&We[15 + cc])
                   + r5[4] * __ldg(&We[20 + cc]);
        }
    }
    float rbe[5], rp2[5];
    #pragma unroll
    for (int c = 0; c < 5; c++) { rbe[c] = __ldg(&be[c]); rp2[c] = __ldg(&p2[c]); }

    cudaGridDependencySynchronize();     // k2 done: S (and dv, x1, Wc) valid

    if (t < NN) sdv[t] = g_dv[t];
    #pragma unroll
    for (int r = 0; r < 5; ++r) {
        int u = t + r * 128;
        if (u < NN * 5) sS[u] = g_S[u];
    }
    if (t < HID) sx1r[t] = g_x1[i * HID + t];
    if (t < 64) reinterpret_cast<float4*>(sWc)[t] = reinterpret_cast<const float4*>(g_Wc)[t];
    __syncthreads();

    float dvi = sdv[i];
    float partv = 0.f;
    if (eact) {
        float dvk = sdv[kn];
        float inv = 1.f / (fmaxf(fmaxf(dvi, dvk), 0.f) + 1e-10f);
        #pragma unroll
        for (int c = 0; c < 5; c++) {
            float hh = gg[c] * inv;
            float v = dvi * (sS[i * 5 + c] - hh) + dvk * (sS[kn * 5 + c] - hh) + rbe[c];
            partv += fmaxf(v, 0.f) * rp2[c];
        }
    }
    #pragma unroll
    for (int off = 16; off; off >>= 1) partv += __shfl_xor_sync(0xffffffffu, partv, off);
    if (lane == 0) wred[wq] = partv;
    __syncthreads();

    {
        int o = wq;
        float qv = sx1r[lane] * sWc[lane * 4 + o] + sx1r[lane + 32] * sWc[(lane + 32) * 4 + o];
        #pragma unroll
        for (int off = 16; off; off >>= 1) qv += __shfl_xor_sync(0xffffffffu, qv, off);
        if (lane == 0) {
            float D = wred[0] + wred[1] + wred[2] + wred[3];
            atomicAdd(&out[o], D * qv * (1.0f / (float)NN));
        }
    }
}

extern "C" void kernel_launch(void* const* d_in, const int* in_sizes, int n_in,
                              void* d_out, int out_size) {
    const float* enc   = (const float*)d_in[0];
    const float* ea    = (const float*)d_in[1];
    // d_in[2] = edge_index (triu order, closed-form reproduced) — unused
    const float* W_enc = (const float*)d_in[3];
    const float* b_enc = (const float*)d_in[4];
    const float* W1    = (const float*)d_in[5];
    const float* b1    = (const float*)d_in[6];
    const float* p1    = (const float*)d_in[7];
    const float* We    = (const float*)d_in[8];
    const float* be    = (const float*)d_in[9];
    const float* pe    = (const float*)d_in[10];
    const float* W2    = (const float*)d_in[11];
    const float* b2    = (const float*)d_in[12];
    const float* p2    = (const float*)d_in[13];
    const float* Wl    = (const float*)d_in[14];
    const float* bl    = (const float*)d_in[15];
    float* out = (float*)d_out;

    cudaLaunchAttribute attr[1];
    attr[0].id = cudaLaunchAttributeProgrammaticStreamSerialization;
    attr[0].val.programmaticStreamSerializationAllowed = 1;

    k1<<<NN, 512>>>(enc, ea, W_enc, b_enc, W1, b1, p1, pe);
    {
        cudaLaunchConfig_t cfg = {};
        cfg.gridDim = dim3(NN + 2); cfg.blockDim = dim3(128);
        cfg.attrs = attr; cfg.numAttrs = 1; cfg.stream = 0;
        cudaLaunchKernelEx(&cfg, k2, ea, We, W2, b2, Wl, bl, out);
    }
    {
        cudaLaunchConfig_t cfg = {};
        cfg.gridDim = dim3(NN); cfg.blockDim = dim3(128);
        cfg.attrs = attr; cfg.numAttrs = 1; cfg.stream = 0;
        cudaLaunchKernelEx(&cfg, k3, ea, We, be, p2, out);
    }
}

// round 17
// speedup vs baseline: 1.0025x; 1.0025x over previous
#include <cuda_runtime.h>

#define NN   116
#define HID  64
#define ENCD 122

// ---- device scratch ----
__device__ float g_dv[NN];
__device__ __align__(16) float g_x1[NN * HID];
__device__ __align__(16) float g_Wc[HID * 4];    // W2 @ Wl
__device__ float g_S[NN * 5];

__device__ __forceinline__ int rowoff(int a) { return a * (231 - a) / 2; }
__device__ __forceinline__ int eix(int a, int b) { return rowoff(a) + (b - a - 1); }

// ============================================================================
// K1 (116 x 512): block per node i. R15 structure (coalesced float2 loads,
// smem partial reductions) minus gE writes (k2/k3 recompute from ea).
// ============================================================================
__global__ void __launch_bounds__(512, 1) k1(
    const float* __restrict__ enc, const float* __restrict__ ea,
    const float* __restrict__ W_enc, const float* __restrict__ b_enc,
    const float* __restrict__ W1, const float* __restrict__ b1,
    const float* __restrict__ p1, const float* __restrict__ pe)
{
    __shared__ float sd1[120];            // [115..119] = 0
    __shared__ float sMp[8 * 123];
    __shared__ float sM[128];             // [122]=bias lane, [123..127]=0
    __shared__ float sp[1024];
    __shared__ float sy[64];
    __shared__ float sx1[64];

    const int i = blockIdx.x, t = threadIdx.x;
    const int g8 = t >> 6, c2 = t & 63;   // M stage: row-chunk g8, col-pair c2
    const int gr = t >> 5, mp = t & 31;   // y/x1 stage: c-chunk gr, m-pair mp

    // ---------- Phase 0: batch-issue ALL global loads (vectorized) ----------
    float a5[5];
    const bool eact = t < 115;
    if (eact) {
        int k = t + (t >= i);
        int a = min(i, k), b = max(i, k);
        const float* A = ea + eix(a, b) * 5;
        #pragma unroll
        for (int c = 0; c < 5; c++) a5[c] = A[c];
    }
    // enc: col pair (2c2, 2c2+1), 15-row slice g8 — warp-contiguous float2
    float2 rE2[15];
    #pragma unroll
    for (int j = 0; j < 15; ++j) {
        int u = g8 * 15 + j;
        float2 v = make_float2(0.f, 0.f);
        if (c2 < 61 && u < 115) {
            int k = u + (u >= i);
            v = *reinterpret_cast<const float2*>(enc + k * ENCD + 2 * c2);
        }
        rE2[j] = v;
    }
    // y-stage weights: c = gr*8+j rows of [W_enc; b_enc; 0], m-pair mp (coalesced)
    float2 rWz2[8];
    #pragma unroll
    for (int j = 0; j < 8; ++j) {
        int c = gr * 8 + j;
        float2 v = make_float2(0.f, 0.f);
        if (c < 122)       v = *reinterpret_cast<const float2*>(W_enc + c * HID + 2 * mp);
        else if (c == 122) v = *reinterpret_cast<const float2*>(b_enc + 2 * mp);
        rWz2[j] = v;
    }
    // x1-stage weights: c = gr*4+j rows of W1, m-pair mp
    float2 rW12[4];
    #pragma unroll
    for (int j = 0; j < 4; ++j) {
        int c = gr * 4 + j;
        rW12[j] = *reinterpret_cast<const float2*>(W1 + c * HID + 2 * mp);
    }
    float rb1 = (t < 64) ? b1[t] : 0.f;
    float rpe0 = 0.f, rpe1 = 0.f;
    if (t < 32) { rpe0 = pe[t]; rpe1 = pe[t + 32]; }

    // ---------- d1 ----------
    if (eact) {
        sd1[t] = a5[0] * __ldg(&p1[0]) + a5[1] * __ldg(&p1[1]) + a5[2] * __ldg(&p1[2])
               + a5[3] * __ldg(&p1[3]) + a5[4] * __ldg(&p1[4]);
    }
    if (t >= 115 && t < 120) sd1[t] = 0.f;
    __syncthreads();

    // ---------- M stage (float2 col pairs, 8 row-chunks) ----------
    if (c2 < 61) {
        float s0 = 0.f, s1 = 0.f;
        #pragma unroll
        for (int j = 0; j < 15; ++j) {
            float d = sd1[g8 * 15 + j];
            s0 += rE2[j].x * d;
            s1 += rE2[j].y * d;
        }
        sMp[g8 * 123 + 2 * c2]     = s0;
        sMp[g8 * 123 + 2 * c2 + 1] = s1;
    } else if (c2 == 61) {                // bias lane: plain sum of d1
        float s = 0.f;
        #pragma unroll
        for (int j = 0; j < 15; ++j) {
            int u = g8 * 15 + j;
            if (u < 115) s += sd1[u];
        }
        sMp[g8 * 123 + 122] = s;
    }
    __syncthreads();
    if (t < 123) {
        float s = 0.f;
        #pragma unroll
        for (int q = 0; q < 8; ++q) s += sMp[q * 123 + t];
        sM[t] = s;
    }
    if (t >= 123 && t < 128) sM[t] = 0.f;
    __syncthreads();

    // ---------- y = M @ [W_enc; b_enc; 0] : 16 c-chunks x m-pairs ----------
    {
        float s0 = 0.f, s1 = 0.f;
        #pragma unroll
        for (int j = 0; j < 8; ++j) {
            float mv = sM[gr * 8 + j];
            s0 += mv * rWz2[j].x;
            s1 += mv * rWz2[j].y;
        }
        sp[gr * 64 + 2 * mp]     = s0;
        sp[gr * 64 + 2 * mp + 1] = s1;
    }
    __syncthreads();
    if (t < HID) {
        float s = 0.f;
        #pragma unroll
        for (int q = 0; q < 16; ++q) s += sp[q * 64 + t];
        sy[t] = s;
    }
    __syncthreads();

    // ---------- x1 = relu(b1 + y @ W1) : 16 c-chunks x m-pairs ----------
    {
        float s0 = 0.f, s1 = 0.f;
        #pragma unroll
        for (int j = 0; j < 4; ++j) {
            float yv = sy[gr * 4 + j];
            s0 += yv * rW12[j].x;
            s1 += yv * rW12[j].y;
        }
        sp[gr * 64 + 2 * mp]     = s0;
        sp[gr * 64 + 2 * mp + 1] = s1;
    }
    __syncthreads();
    if (t < HID) {
        float s = 0.f;
        #pragma unroll
        for (int q = 0; q < 16; ++q) s += sp[q * 64 + t];
        float x = fmaxf(rb1 + s, 0.f);
        sx1[t] = x;
        g_x1[i * HID + t] = x;
    }
    __syncthreads();

    // ---------- dv = x1 . pe ----------
    if (t < 32) {
        float s = sx1[t] * rpe0 + sx1[t + 32] * rpe1;
        #pragma unroll
        for (int off = 16; off; off >>= 1) s += __shfl_xor_sync(0xffffffffu, s, off);
        if (t == 0) g_dv[i] = s;
    }
}

// ============================================================================
// K2 (PDL): blocks 0..115: S[i,c] with gg recomputed from ea in PREAMBLE
// (overlaps k1). Blocks 116,117: Wc = W2@Wl + bias seed (no sync needed).
// ============================================================================
__global__ void __launch_bounds__(128, 1) k2(
    const float* __restrict__ ea, const float* __restrict__ We,
    const float* __restrict__ W2, const float* __restrict__ b2,
    const float* __restrict__ Wl, const float* __restrict__ bl,
    float* __restrict__ out)
{
    const int i = blockIdx.x, t = threadIdx.x;

    if (i >= NN) {
        int idx = (i - NN) * 128 + t;    // 0..255
        int k = idx >> 2, o = idx & 3;
        float s = 0.f;
        #pragma unroll
        for (int mm = 0; mm < HID; mm++) s += W2[k * HID + mm] * Wl[mm * 4 + o];
        g_Wc[idx] = s;
        if (i == NN && t < 4) {
            float v = bl[t];
            #pragma unroll
            for (int mm = 0; mm < HID; mm++) v += b2[mm] * Wl[mm * 4 + t];
            out[t] = v;
        }
        return;
    }

    __shared__ float sdv[NN];
    __shared__ float wsum[4 * 5];
    const int wq = t >> 5, lane = t & 31;

    // ---- PREAMBLE (overlaps k1): gg from ea + We ----
    float gg[5] = {0.f, 0.f, 0.f, 0.f, 0.f};
    int kn = 0;
    const bool eact = t < 115;
    if (eact) {
        kn = t + (t >= i);
        int a = min(i, kn), b = max(i, kn);
        const float* A = ea + eix(a, b) * 5;
        float r5[5];
        #pragma unroll
        for (int c = 0; c < 5; c++) r5[c] = fmaxf(A[c], 0.f);
        #pragma unroll
        for (int cc = 0; cc < 5; cc++) {
            gg[cc] = r5[0] * __ldg(&We[cc]) + r5[1] * __ldg(&We[5 + cc])
                   + r5[2] * __ldg(&We[10 + cc]) + r5[3] * __ldg(&We[15 + cc])
                   + r5[4] * __ldg(&We[20 + cc]);
        }
    }

    cudaGridDependencySynchronize();     // k1 done: dv valid

    if (t < NN) sdv[t] = g_dv[t];
    __syncthreads();

    float s5[5] = {0.f, 0.f, 0.f, 0.f, 0.f};
    if (eact) {
        float inv = 1.f / (fmaxf(fmaxf(sdv[i], sdv[kn]), 0.f) + 1e-10f);
        #pragma unroll
        for (int c = 0; c < 5; c++) s5[c] = gg[c] * inv;
    }
    #pragma unroll
    for (int c = 0; c < 5; c++) {
        #pragma unroll
        for (int off = 16; off; off >>= 1) s5[c] += __shfl_xor_sync(0xffffffffu, s5[c], off);
        if (lane == 0) wsum[wq * 5 + c] = s5[c];
    }
    __syncthreads();
    if (t < 5) g_S[i * 5 + t] = wsum[t] + wsum[5 + t] + wsum[10 + t] + wsum[15 + t];
}

// ============================================================================
// K3 (PDL): gg preamble (overlaps k2); post-sync: dv/S/x1/Wc batched loads,
// D[i], q = x1@Wc, atomic out.
// ============================================================================
__global__ void __launch_bounds__(128, 1) k3(
    const float* __restrict__ ea, const float* __restrict__ We,
    const float* __restrict__ be, const float* __restrict__ p2,
    float* __restrict__ out)
{
    __shared__ float sdv[NN];
    __shared__ float sS[NN * 5];
    __shared__ float sx1r[HID];
    __shared__ __align__(16) float sWc[HID * 4];
    __shared__ float wred[4];
    const int i = blockIdx.x, t = threadIdx.x;
    const int wq = t >> 5, lane = t & 31;

    // ---- PREAMBLE: gg from ea + We, constants ----
    float gg[5] = {0.f, 0.f, 0.f, 0.f, 0.f};
    int kn = 0;
    const bool eact = t < 115;
    if (eact) {
        kn = t + (t >= i);
        int a = min(i, kn), b = max(i, kn);
        const float* A = ea + eix(a, b) * 5;
        float r5[5];
        #pragma unroll
        for (int c = 0; c < 5; c++) r5[c] = fmaxf(A[c], 0.f);
        #pragma unroll
        for (int cc = 0; cc < 5; cc++) {
            gg[cc] = r5[0] * __ldg(&We[cc]) + r5[1] * __ldg(&We[5 + cc])
                   + r5[2] * __ldg(&We[10 + cc]) + r5[3] * __ldg(&We[15 + cc])
                   + r5[4] * __ldg(&We[20 + cc]);
        }
    }
    float rbe[5], rp2[5];
    #pragma unroll
    for (int c = 0; c < 5; c++) { rbe[c] = __ldg(&be[c]); rp2[c] = __ldg(&p2[c]); }

    cudaGridDependencySynchronize();     // k2 done: S (and dv, x1, Wc) valid

    if (t < NN) sdv[t] = g_dv[t];
    #pragma unroll
    for (int r = 0; r < 5; ++r) {
        int u = t + r * 128;
        if (u < NN * 5) sS[u] = g_S[u];
    }
    if (t < HID) sx1r[t] = g_x1[i * HID + t];
    if (t < 64) reinterpret_cast<float4*>(sWc)[t] = reinterpret_cast<const float4*>(g_Wc)[t];
    __syncthreads();

    float dvi = sdv[i];
    float partv = 0.f;
    if (eact) {
        float dvk = sdv[kn];
        float inv = 1.f / (fmaxf(fmaxf(dvi, dvk), 0.f) + 1e-10f);
        #pragma unroll
        for (int c = 0; c < 5; c++) {
            float hh = gg[c] * inv;
            float v = dvi * (sS[i * 5 + c] - hh) + dvk * (sS[kn * 5 + c] - hh) + rbe[c];
            partv += fmaxf(v, 0.f) * rp2[c];
        }
    }
    #pragma unroll
    for (int off = 16; off; off >>= 1) partv += __shfl_xor_sync(0xffffffffu, partv, off);
    if (lane == 0) wred[wq] = partv;
    __syncthreads();

    {
        int o = wq;
        float qv = sx1r[lane] * sWc[lane * 4 + o] + sx1r[lane + 32] * sWc[(lane + 32) * 4 + o];
        #pragma unroll
        for (int off = 16; off; off >>= 1) qv += __shfl_xor_sync(0xffffffffu, qv, off);
        if (lane == 0) {
            float D = wred[0] + wred[1] + wred[2] + wred[3];
            atomicAdd(&out[o], D * qv * (1.0f / (float)NN));
        }
    }
}

extern "C" void kernel_launch(void* const* d_in, const int* in_sizes, int n_in,
                              void* d_out, int out_size) {
    const float* enc   = (const float*)d_in[0];
    const float* ea    = (const float*)d_in[1];
    // d_in[2] = edge_index (triu order, closed-form reproduced) — unused
    const float* W_enc = (const float*)d_in[3];
    const float* b_enc = (const float*)d_in[4];
    const float* W1    = (const float*)d_in[5];
    const float* b1    = (const float*)d_in[6];
    const float* p1    = (const float*)d_in[7];
    const float* We    = (const float*)d_in[8];
    const float* be    = (const float*)d_in[9];
    const float* pe    = (const float*)d_in[10];
    const float* W2    = (const float*)d_in[11];
    const float* b2    = (const float*)d_in[12];
    const float* p2    = (const float*)d_in[13];
    const float* Wl    = (const float*)d_in[14];
    const float* bl    = (const float*)d_in[15];
    float* out = (float*)d_out;

    cudaLaunchAttribute attr[1];
    attr[0].id = cudaLaunchAttributeProgrammaticStreamSerialization;
    attr[0].val.programmaticStreamSerializationAllowed = 1;

    k1<<<NN, 512>>>(enc, ea, W_enc, b_enc, W1, b1, p1, pe);
    {
        cudaLaunchConfig_t cfg = {};
        cfg.gridDim = dim3(NN + 2); cfg.blockDim = dim3(128);
        cfg.attrs = attr; cfg.numAttrs = 1; cfg.stream = 0;
        cudaLaunchKernelEx(&cfg, k2, ea, We, W2, b2, Wl, bl, out);
    }
    {
        cudaLaunchConfig_t cfg = {};
        cfg.gridDim = dim3(NN); cfg.blockDim = dim3(128);
        cfg.attrs = attr; cfg.numAttrs = 1; cfg.stream = 0;
        cudaLaunchKernelEx(&cfg, k3, ea, We, be, p2, out);
    }
}